// round 6
// baseline (speedup 1.0000x reference)
#include <cuda_runtime.h>
#include <cstdint>

// ============================================================================
// y[128, 11008] = x[128,4096] @ W[11008,4096]^T * scale + bias
// w_q arrives as int32 (harness widens int8 -> int32). Packed to s8 in-flight.
// Dual-level int8 quantization of x:  x ~ s_m*(q1 + q2/254)
// GEMM via mma.sync.m16n8k32.s8, fp32 epilogue.
// R6: K_STAGE=256, NSTAGES=2, distance-1 prefetch -> 16 steps (half barriers).
// 138 CTAs x 640 threads (single wave), 4(M)x5(N) warps, warp tile 32x16.
// ============================================================================

#define M_ROWS 128
#define K_DIM  4096
#define N_DIM  11008
#define N_TILE 80
#define N_BLOCKS ((N_DIM + N_TILE - 1) / N_TILE)   // 138
#define K_STAGE 256
#define NSTAGES 2
#define NUM_STEPS (K_DIM / K_STAGE)        // 16
#define NTHREADS 640

#define SMEM_ROW 272                       // 256 + 16 pad (conflict-free LDS)
#define A_TILE_BYTES (M_ROWS * SMEM_ROW)   // 34816
#define B_TILE_BYTES (N_TILE * SMEM_ROW)   // 21760
#define STAGE_BYTES  (2 * A_TILE_BYTES + B_TILE_BYTES)   // 91392
#define SMEM_TOTAL   (NSTAGES * STAGE_BYTES)             // 182784

#define B_OFF  (2 * A_TILE_BYTES)

// ---- scratch (no cudaMalloc allowed) ----
__device__ __align__(1024) int8_t g_q1[M_ROWS * K_DIM];
__device__ __align__(1024) int8_t g_q2[M_ROWS * K_DIM];
__device__ float g_xscale[M_ROWS];

// ============================================================================
// helpers
// ============================================================================
__device__ __forceinline__ uint32_t smem_u32(const void* p) {
    uint32_t a;
    asm("{ .reg .u64 t; cvta.to.shared.u64 t, %1; cvt.u32.u64 %0, t; }"
        : "=r"(a) : "l"(p));
    return a;
}
__device__ __forceinline__ void cp16(uint32_t dst, const void* src) {
    asm volatile("cp.async.cg.shared.global [%0], [%1], 16;"
                 :: "r"(dst), "l"(src) : "memory");
}
__device__ __forceinline__ void cp_commit() {
    asm volatile("cp.async.commit_group;" ::: "memory");
}
template <int N>
__device__ __forceinline__ void cp_wait() {
    asm volatile("cp.async.wait_group %0;" :: "n"(N) : "memory");
}
__device__ __forceinline__ void mma_s8(int* d, const uint32_t* a, const uint32_t* b) {
    asm volatile(
        "mma.sync.aligned.m16n8k32.row.col.s32.s8.s8.s32 "
        "{%0,%1,%2,%3}, {%4,%5,%6,%7}, {%8,%9}, {%0,%1,%2,%3};"
        : "+r"(d[0]), "+r"(d[1]), "+r"(d[2]), "+r"(d[3])
        : "r"(a[0]), "r"(a[1]), "r"(a[2]), "r"(a[3]), "r"(b[0]), "r"(b[1]));
}
__device__ __forceinline__ uint32_t pack4(int4 v) {
    uint32_t lo = __byte_perm((uint32_t)v.x, (uint32_t)v.y, 0x0040);
    uint32_t hi = __byte_perm((uint32_t)v.z, (uint32_t)v.w, 0x0040);
    return __byte_perm(lo, hi, 0x5410);
}

// ============================================================================
// Kernel 1: quantize x rows -> (q1, q2) int8 + per-row scale
// ============================================================================
__global__ __launch_bounds__(128) void quant_x_kernel(const float* __restrict__ x) {
    int m = blockIdx.x;
    int tid = threadIdx.x;
    const float4* xr = reinterpret_cast<const float4*>(x + (size_t)m * K_DIM);

    float4 v[8];
    float vmax = 0.f;
#pragma unroll
    for (int i = 0; i < 8; i++) {
        v[i] = xr[tid + i * 128];
        vmax = fmaxf(vmax, fmaxf(fmaxf(fabsf(v[i].x), fabsf(v[i].y)),
                                 fmaxf(fabsf(v[i].z), fabsf(v[i].w))));
    }
#pragma unroll
    for (int o = 16; o > 0; o >>= 1)
        vmax = fmaxf(vmax, __shfl_xor_sync(0xffffffffu, vmax, o));

    __shared__ float smax[4];
    if ((tid & 31) == 0) smax[tid >> 5] = vmax;
    __syncthreads();
    vmax = fmaxf(fmaxf(smax[0], smax[1]), fmaxf(smax[2], smax[3]));

    float inv = (vmax > 0.f) ? (127.0f / vmax) : 0.0f;
    float sm  = (vmax > 0.f) ? (vmax / 127.0f) : 1.0f;
    if (tid == 0) g_xscale[m] = sm;

    char4* o1 = reinterpret_cast<char4*>(g_q1 + (size_t)m * K_DIM);
    char4* o2 = reinterpret_cast<char4*>(g_q2 + (size_t)m * K_DIM);

#pragma unroll
    for (int i = 0; i < 8; i++) {
        float t[4] = {v[i].x * inv, v[i].y * inv, v[i].z * inv, v[i].w * inv};
        char q1c[4], q2c[4];
#pragma unroll
        for (int j = 0; j < 4; j++) {
            float q1 = rintf(t[j]);
            float q2 = rintf((t[j] - q1) * 254.0f);
            q1c[j] = (char)(int)q1;
            q2c[j] = (char)(int)q2;
        }
        o1[tid + i * 128] = make_char4(q1c[0], q1c[1], q1c[2], q1c[3]);
        o2[tid + i * 128] = make_char4(q2c[0], q2c[1], q2c[2], q2c[3]);
    }
}

// ============================================================================
// Kernel 2: GEMM. 138 CTAs x 640 threads. CTA tile 128(M) x 80(N).
// 4x5 warp grid, warp tile 32x16. 2-stage ring, distance-1 prefetch:
//   A1/A2 (int8 g_q1/g_q2): cp.async (threads 0..511, 8 x 16B per stage)
//   B (int32 W): LDG.128 -> pack s8 -> STS right after top-of-step sync
// ============================================================================
__global__ __launch_bounds__(NTHREADS, 1) void gemm_i8_kernel(
    const int* __restrict__ w32,
    const float* __restrict__ scale,
    const float* __restrict__ bias,
    float* __restrict__ out)
{
    extern __shared__ char smem[];
    const uint32_t sb = smem_u32(smem);
    const int tid = threadIdx.x;
    const int wid = tid >> 5;
    const int lane = tid & 31;
    const int wm = wid & 3;        // warp M index (0..3)
    const int wn = wid >> 2;       // warp N index (0..4)
    const int n_base = blockIdx.x * N_TILE;

    // ---- A-side cp.async (threads 0..511, 8 x 16B per stage) ---------------
    uint32_t cpA_dst[8];
    const int8_t* cpA_src[8];
    if (tid < 512) {
#pragma unroll
        for (int i = 0; i < 8; i++) {
            int c = tid + i * 512;           // [0, 4096)
            int which = c >> 11;             // 0:A1 1:A2
            int r = (c >> 4) & 127;          // m row 0..127
            int col = (c & 15) * 16;         // k byte 0..240
            cpA_dst[i] = sb + which * A_TILE_BYTES + r * SMEM_ROW + col;
            cpA_src[i] = (which ? g_q2 : g_q1) + (size_t)r * K_DIM + col;
        }
    }
    auto issueA = [&](int s) {
        if (tid < 512) {
            uint32_t buf_off = (uint32_t)((s & (NSTAGES - 1)) * STAGE_BYTES);
            int k0 = s * K_STAGE;
#pragma unroll
            for (int i = 0; i < 8; i++)
                cp16(cpA_dst[i] + buf_off, cpA_src[i] + k0);
            cp_commit();
        }
    };

    // ---- B-side: 8 x LDG.128 -> pack -> 8 x STS per stage ------------------
    const int wr = tid >> 5;            // base n-row 0..19 (rows wr + 20j)
    const int c16 = lane * 4;           // int32 idx (= packed byte col), half h adds 128
    const int* wsrc[4];
#pragma unroll
    for (int j = 0; j < 4; j++) {
        int rg = n_base + wr + 20 * j;
        if (rg > N_DIM - 1) rg = N_DIM - 1;   // clamp (ragged last tile)
        wsrc[j] = w32 + (size_t)rg * K_DIM + c16;
    }
    auto loadB = [&](int s) {
        const int k0 = s * K_STAGE;
        char* dst = smem + (s & (NSTAGES - 1)) * STAGE_BYTES + B_OFF
                         + wr * SMEM_ROW + c16;
        int4 b[8];
#pragma unroll
        for (int j = 0; j < 4; j++) {
#pragma unroll
            for (int h = 0; h < 2; h++)
                b[j * 2 + h] = *reinterpret_cast<const int4*>(wsrc[j] + k0 + h * 128);
        }
#pragma unroll
        for (int j = 0; j < 4; j++) {
#pragma unroll
            for (int h = 0; h < 2; h++)
                *reinterpret_cast<uint32_t*>(dst + j * 20 * SMEM_ROW + h * 128) =
                    pack4(b[j * 2 + h]);
        }
    };

    // ---- prologue: stage 0 --------------------------------------------------
    issueA(0);
    loadB(0);

    // ---- per-lane fragment base pointers (PTX m16n8k32.s8 spec) ------------
    const int g  = lane >> 2;
    const int t4 = (lane & 3) * 4;
    const char* A1p = smem + (wm * 32 + g) * SMEM_ROW + t4;
    const char* Bp  = smem + B_OFF + (wn * 16 + g) * SMEM_ROW + t4;

    int acc1[2][2][4] = {};
    int acc2[2][2][4] = {};

    // ---- main loop ---------------------------------------------------------
    for (int s = 0; s < NUM_STEPS; s++) {
        cp_wait<0>();          // A stage s landed (participating threads)
        __syncthreads();       // publish everyone's A + B(stage s)

        if (s + 1 < NUM_STEPS) { loadB(s + 1); issueA(s + 1); }

        const int buf = (s & (NSTAGES - 1)) * STAGE_BYTES;
#pragma unroll
        for (int ks = 0; ks < 8; ks++) {
            const int off = buf + ks * 32;
            uint32_t a1f[2][4], a2f[2][4], bfr[2][2];
#pragma unroll
            for (int mf = 0; mf < 2; mf++) {
                const char* r1 = A1p + off + mf * (16 * SMEM_ROW);
                a1f[mf][0] = *(const uint32_t*)(r1);
                a1f[mf][1] = *(const uint32_t*)(r1 + 8 * SMEM_ROW);
                a1f[mf][2] = *(const uint32_t*)(r1 + 16);
                a1f[mf][3] = *(const uint32_t*)(r1 + 8 * SMEM_ROW + 16);
                const char* r2 = r1 + A_TILE_BYTES;
                a2f[mf][0] = *(const uint32_t*)(r2);
                a2f[mf][1] = *(const uint32_t*)(r2 + 8 * SMEM_ROW);
                a2f[mf][2] = *(const uint32_t*)(r2 + 16);
                a2f[mf][3] = *(const uint32_t*)(r2 + 8 * SMEM_ROW + 16);
            }
#pragma unroll
            for (int nf = 0; nf < 2; nf++) {
                const char* rb = Bp + off + nf * (8 * SMEM_ROW);
                bfr[nf][0] = *(const uint32_t*)(rb);
                bfr[nf][1] = *(const uint32_t*)(rb + 16);
            }
#pragma unroll
            for (int mf = 0; mf < 2; mf++) {
#pragma unroll
                for (int nf = 0; nf < 2; nf++) {
                    mma_s8(acc1[mf][nf], a1f[mf], bfr[nf]);
                    mma_s8(acc2[mf][nf], a2f[mf], bfr[nf]);
                }
            }
        }
    }

    // ---- epilogue ----------------------------------------------------------
    const float sw = __ldg(scale);
    const int mrow0 = wm * 32 + g;
#pragma unroll
    for (int mf = 0; mf < 2; mf++) {
        int m0 = mrow0 + mf * 16;
        float f1a = sw * g_xscale[m0];
        float f1b = sw * g_xscale[m0 + 8];
        float f2a = f1a * (1.0f / 254.0f);
        float f2b = f1b * (1.0f / 254.0f);
#pragma unroll
        for (int nf = 0; nf < 2; nf++) {
            int n = n_base + wn * 16 + nf * 8 + 2 * (lane & 3);
            if (n < N_DIM) {
                float2 bv = __ldg(reinterpret_cast<const float2*>(bias + n));
                float2 o0, o1;
                o0.x = (float)acc1[mf][nf][0] * f1a + (float)acc2[mf][nf][0] * f2a + bv.x;
                o0.y = (float)acc1[mf][nf][1] * f1a + (float)acc2[mf][nf][1] * f2a + bv.y;
                o1.x = (float)acc1[mf][nf][2] * f1b + (float)acc2[mf][nf][2] * f2b + bv.x;
                o1.y = (float)acc1[mf][nf][3] * f1b + (float)acc2[mf][nf][3] * f2b + bv.y;
                *reinterpret_cast<float2*>(out + (size_t)m0 * N_DIM + n) = o0;
                *reinterpret_cast<float2*>(out + (size_t)(m0 + 8) * N_DIM + n) = o1;
            }
        }
    }
}

// ============================================================================
// Host launcher — inputs identified by element count (order-robust)
// ============================================================================
extern "C" void kernel_launch(void* const* d_in, const int* in_sizes, int n_in,
                              void* d_out, int out_size) {
    const float* x     = nullptr;
    const int*   w32   = nullptr;    // int8 weights widened to int32 by harness
    const float* scale = nullptr;
    const float* bias  = nullptr;
    for (int i = 0; i < n_in; i++) {
        switch (in_sizes[i]) {
            case M_ROWS * K_DIM: x     = (const float*)d_in[i]; break;  // 524288
            case N_DIM * K_DIM:  w32   = (const int*)d_in[i];   break;  // 45088768
            case 1:              scale = (const float*)d_in[i]; break;
            case N_DIM:          bias  = (const float*)d_in[i]; break;  // 11008
        }
    }
    float* out = (float*)d_out;

    cudaFuncSetAttribute(gemm_i8_kernel,
                         cudaFuncAttributeMaxDynamicSharedMemorySize, SMEM_TOTAL);

    quant_x_kernel<<<M_ROWS, 128>>>(x);
    gemm_i8_kernel<<<N_BLOCKS, NTHREADS, SMEM_TOTAL>>>(w32, scale, bias, out);
}

// round 7
// speedup vs baseline: 2.3133x; 2.3133x over previous
#include <cuda_runtime.h>
#include <cuda_fp16.h>
#include <cstdint>

// ============================================================================
// y[128, 11008] = x[128,4096] @ W[11008,4096]^T * scale + bias
// w_q arrives as int32 (harness widens int8 -> int32).
// R7: single-pass fp16. x -> fp16 (rel err ~2.8e-4), W int8 exact in fp16.
// GEMM via mma.sync.m16n8k16.f32.f16.f16.f32 (fp32 accum), fp32 epilogue.
// 138 CTAs x 640 threads (single wave), 4(M)x5(N) warps, warp tile 32x16.
// R5-proven schedule: 4 stages, K_STAGE=128, distance-2, STS after compute.
// ============================================================================

#define M_ROWS 128
#define K_DIM  4096
#define N_DIM  11008
#define N_TILE 80
#define N_BLOCKS ((N_DIM + N_TILE - 1) / N_TILE)   // 138
#define K_STAGE 128                        // k elements per stage
#define NSTAGES 4
#define NUM_STEPS (K_DIM / K_STAGE)        // 32
#define NTHREADS 640

#define SMEM_ROW 272                       // 256B data + 16 pad (conflict-free)
#define A_TILE_BYTES (M_ROWS * SMEM_ROW)   // 34816
#define B_TILE_BYTES (N_TILE * SMEM_ROW)   // 21760
#define STAGE_BYTES  (A_TILE_BYTES + B_TILE_BYTES)       // 56576
#define SMEM_TOTAL   (NSTAGES * STAGE_BYTES)             // 226304 (< 227KB cap)

#define B_OFF  A_TILE_BYTES

// ---- scratch (no cudaMalloc allowed) ----
__device__ __align__(1024) __half g_xh[M_ROWS * K_DIM];

// ============================================================================
// helpers
// ============================================================================
__device__ __forceinline__ uint32_t smem_u32(const void* p) {
    uint32_t a;
    asm("{ .reg .u64 t; cvta.to.shared.u64 t, %1; cvt.u32.u64 %0, t; }"
        : "=r"(a) : "l"(p));
    return a;
}
__device__ __forceinline__ void cp16(uint32_t dst, const void* src) {
    asm volatile("cp.async.cg.shared.global [%0], [%1], 16;"
                 :: "r"(dst), "l"(src) : "memory");
}
__device__ __forceinline__ void cp_commit() {
    asm volatile("cp.async.commit_group;" ::: "memory");
}
template <int N>
__device__ __forceinline__ void cp_wait() {
    asm volatile("cp.async.wait_group %0;" :: "n"(N) : "memory");
}
__device__ __forceinline__ void mma_f16(float* d, const uint32_t* a, const uint32_t* b) {
    asm volatile(
        "mma.sync.aligned.m16n8k16.row.col.f32.f16.f16.f32 "
        "{%0,%1,%2,%3}, {%4,%5,%6,%7}, {%8,%9}, {%0,%1,%2,%3};"
        : "+f"(d[0]), "+f"(d[1]), "+f"(d[2]), "+f"(d[3])
        : "r"(a[0]), "r"(a[1]), "r"(a[2]), "r"(a[3]), "r"(b[0]), "r"(b[1]));
}
// two sign-extended int8-in-int32 -> packed half2 (as u32)
__device__ __forceinline__ uint32_t i2h2(int lo, int hi) {
    __half2 h = __halves2half2(__int2half_rn(lo), __int2half_rn(hi));
    return *reinterpret_cast<uint32_t*>(&h);
}

// ============================================================================
// Kernel 1: x (fp32) -> fp16.  65536 threads x 8 elems.
// ============================================================================
__global__ __launch_bounds__(512) void cvt_x_kernel(const float* __restrict__ x) {
    int idx = (blockIdx.x * 512 + threadIdx.x) * 8;
    float4 v0 = *reinterpret_cast<const float4*>(x + idx);
    float4 v1 = *reinterpret_cast<const float4*>(x + idx + 4);
    __half2 h[4];
    h[0] = __floats2half2_rn(v0.x, v0.y);
    h[1] = __floats2half2_rn(v0.z, v0.w);
    h[2] = __floats2half2_rn(v1.x, v1.y);
    h[3] = __floats2half2_rn(v1.z, v1.w);
    *reinterpret_cast<uint4*>(g_xh + idx) = *reinterpret_cast<uint4*>(h);
}

// ============================================================================
// Kernel 2: GEMM. 138 CTAs x 640 threads. CTA tile 128(M) x 80(N).
// 4x5 warp grid, warp tile 32x16. 4-stage ring, distance-2:
//   A (fp16 g_xh): cp.async (threads 0..511, 4 x 16B per stage)
//   B (int32 W): LDG.128 2 ahead -> cvt fp16 -> STS after compute
// Fragment loads: plain LDS at PTX m16n8k16 per-lane coordinates:
//   A (16x16 f16 row-major): a0=(g, 2t..2t+1) a1=(g+8,..) a2/a3 = +8 in k
//   B (16x8 f16 col-major):  b0=(k=2t..2t+1, n=g), b1 = +8 in k
//   C (16x8 f32): c0/c1=(g, 2t/2t+1), c2/c3=(g+8, ..)
// ============================================================================
__global__ __launch_bounds__(NTHREADS, 1) void gemm_f16_kernel(
    const int* __restrict__ w32,
    const float* __restrict__ scale,
    const float* __restrict__ bias,
    float* __restrict__ out)
{
    extern __shared__ char smem[];
    const uint32_t sb = smem_u32(smem);
    const int tid = threadIdx.x;
    const int lane = tid & 31;
    const int wid = tid >> 5;
    const int wm = wid & 3;        // warp M index (0..3)
    const int wn = wid >> 2;       // warp N index (0..4)
    const int n_base = blockIdx.x * N_TILE;

    // ---- A-side cp.async (threads 0..511, 4 x 16B per stage) ---------------
    // A stage = 128 rows x 256 bytes = 2048 chunks of 16B; 16 chunks per row.
    uint32_t cpA_dst[4];
    const __half* cpA_src[4];
    if (tid < 512) {
#pragma unroll
        for (int i = 0; i < 4; i++) {
            int c = tid + i * 512;           // [0, 2048)
            int r = c >> 4;                  // m row 0..127
            int col = (c & 15) * 16;         // byte col 0..240
            cpA_dst[i] = sb + r * SMEM_ROW + col;
            cpA_src[i] = g_xh + (size_t)r * K_DIM + col / 2;
        }
    }
    auto issueA = [&](int s) {
        if (tid < 512) {
            uint32_t buf_off = (uint32_t)((s & (NSTAGES - 1)) * STAGE_BYTES);
            int k0 = s * K_STAGE;
#pragma unroll
            for (int i = 0; i < 4; i++)
                cp16(cpA_dst[i] + buf_off, cpA_src[i] + k0);
            cp_commit();
        }
    };

    // ---- B-side: 4 x LDG.128 per thread per stage --------------------------
    // B tile = 80 rows x 128 k. thread: rows wr+20j (j<4), k = lane*4..lane*4+3
    const int wr = tid >> 5;            // 0..19
    const int c4 = lane * 4;            // int32 (k) index
    const int* wsrc[4];
#pragma unroll
    for (int j = 0; j < 4; j++) {
        int rg = n_base + wr + 20 * j;
        if (rg > N_DIM - 1) rg = N_DIM - 1;   // clamp (ragged last tile)
        wsrc[j] = w32 + (size_t)rg * K_DIM + c4;
    }

    int4 breg[4];
    auto ldgB = [&](int s) {
        const int k0 = s * K_STAGE;
#pragma unroll
        for (int j = 0; j < 4; j++)
            breg[j] = *reinterpret_cast<const int4*>(wsrc[j] + k0);
    };
    auto stsB = [&](int s) {
        // 4 fp16 = 8 bytes per int4, at byte offset row*272 + lane*8
        char* dst = smem + (s & (NSTAGES - 1)) * STAGE_BYTES + B_OFF
                         + wr * SMEM_ROW + lane * 8;
#pragma unroll
        for (int j = 0; j < 4; j++) {
            uint2 hv;
            hv.x = i2h2(breg[j].x, breg[j].y);
            hv.y = i2h2(breg[j].z, breg[j].w);
            *reinterpret_cast<uint2*>(dst + j * 20 * SMEM_ROW) = hv;
        }
    };

    // ---- prologue: stages 0,1 ----------------------------------------------
    issueA(0);
    issueA(1);
    ldgB(0); stsB(0);
    ldgB(1); stsB(1);

    // ---- per-lane fragment base pointers -----------------------------------
    const int g  = lane >> 2;
    const int t4 = (lane & 3) * 4;      // byte offset of f16 pair (2t)*2
    const char* Ap = smem + (wm * 32 + g) * SMEM_ROW + t4;
    const char* Bp = smem + B_OFF + (wn * 16 + g) * SMEM_ROW + t4;

    float acc[2][2][4] = {};

    // ---- main loop ---------------------------------------------------------
    for (int s = 0; s < NUM_STEPS; s++) {
        cp_wait<1>();          // A stage s landed (participating threads)
        __syncthreads();       // publish everyone's A + B(stage s)

        if (s + 2 < NUM_STEPS) { ldgB(s + 2); issueA(s + 2); }
        else if (tid < 512)    { cp_commit(); }   // keep wait accounting sound

        const int buf = (s & (NSTAGES - 1)) * STAGE_BYTES;
#pragma unroll
        for (int ks = 0; ks < 8; ks++) {          // 8 x k16 per stage
            const int off = buf + ks * 32;        // 16 f16 = 32 bytes
            uint32_t af[2][4], bfr[2][2];
#pragma unroll
            for (int mf = 0; mf < 2; mf++) {
                const char* r1 = Ap + off + mf * (16 * SMEM_ROW);
                af[mf][0] = *(const uint32_t*)(r1);
                af[mf][1] = *(const uint32_t*)(r1 + 8 * SMEM_ROW);
                af[mf][2] = *(const uint32_t*)(r1 + 16);
                af[mf][3] = *(const uint32_t*)(r1 + 8 * SMEM_ROW + 16);
            }
#pragma unroll
            for (int nf = 0; nf < 2; nf++) {
                const char* rb = Bp + off + nf * (8 * SMEM_ROW);
                bfr[nf][0] = *(const uint32_t*)(rb);
                bfr[nf][1] = *(const uint32_t*)(rb + 16);
            }
#pragma unroll
            for (int mf = 0; mf < 2; mf++) {
#pragma unroll
                for (int nf = 0; nf < 2; nf++)
                    mma_f16(acc[mf][nf], af[mf], bfr[nf]);
            }
        }

        if (s + 2 < NUM_STEPS) stsB(s + 2);   // ring distance 2 (!= s mod 4)
    }

    // ---- epilogue ----------------------------------------------------------
    const float sw = __ldg(scale);
    const int mrow0 = wm * 32 + g;
#pragma unroll
    for (int mf = 0; mf < 2; mf++) {
        int m0 = mrow0 + mf * 16;
#pragma unroll
        for (int nf = 0; nf < 2; nf++) {
            int n = n_base + wn * 16 + nf * 8 + 2 * (lane & 3);
            if (n < N_DIM) {
                float2 bv = __ldg(reinterpret_cast<const float2*>(bias + n));
                float2 o0, o1;
                o0.x = acc[mf][nf][0] * sw + bv.x;
                o0.y = acc[mf][nf][1] * sw + bv.y;
                o1.x = acc[mf][nf][2] * sw + bv.x;
                o1.y = acc[mf][nf][3] * sw + bv.y;
                *reinterpret_cast<float2*>(out + (size_t)m0 * N_DIM + n) = o0;
                *reinterpret_cast<float2*>(out + (size_t)(m0 + 8) * N_DIM + n) = o1;
            }
        }
    }
}

// ============================================================================
// Host launcher — inputs identified by element count (order-robust)
// ============================================================================
extern "C" void kernel_launch(void* const* d_in, const int* in_sizes, int n_in,
                              void* d_out, int out_size) {
    const float* x     = nullptr;
    const int*   w32   = nullptr;    // int8 weights widened to int32 by harness
    const float* scale = nullptr;
    const float* bias  = nullptr;
    for (int i = 0; i < n_in; i++) {
        switch (in_sizes[i]) {
            case M_ROWS * K_DIM: x     = (const float*)d_in[i]; break;  // 524288
            case N_DIM * K_DIM:  w32   = (const int*)d_in[i];   break;  // 45088768
            case 1:              scale = (const float*)d_in[i]; break;
            case N_DIM:          bias  = (const float*)d_in[i]; break;  // 11008
        }
    }
    float* out = (float*)d_out;

    cudaFuncSetAttribute(gemm_f16_kernel,
                         cudaFuncAttributeMaxDynamicSharedMemorySize, SMEM_TOTAL);

    cvt_x_kernel<<<M_ROWS, 512>>>(x);
    gemm_f16_kernel<<<N_BLOCKS, NTHREADS, SMEM_TOTAL>>>(w32, scale, bias, out);
}

// round 8
// speedup vs baseline: 2.4389x; 1.0543x over previous
#include <cuda_runtime.h>
#include <cuda_fp16.h>
#include <cstdint>

// ============================================================================
// y[128, 11008] = x[128,4096] @ W[11008,4096]^T * scale + bias
// w_q arrives as int32 (harness widens int8 -> int32).
// fp16 single-pass: x -> fp16 (rel err ~2e-4), W int8 exact in fp16.
// GEMM via mma.sync.m16n8k16.f32.f16.f16.f32, fragments via ldmatrix.x4.
// 138 CTAs x 640 threads (single wave), 4(M)x5(N) warps, warp tile 32x16.
// 4 stages, K_STAGE=128, distance-2, STS after compute, frag prefetch ks+1.
// ============================================================================

#define M_ROWS 128
#define K_DIM  4096
#define N_DIM  11008
#define N_TILE 80
#define N_BLOCKS ((N_DIM + N_TILE - 1) / N_TILE)   // 138
#define K_STAGE 128                        // k elements per stage
#define NSTAGES 4
#define NUM_STEPS (K_DIM / K_STAGE)        // 32
#define NTHREADS 640

#define SMEM_ROW 272                       // 256B data + 16 pad
#define A_TILE_BYTES (M_ROWS * SMEM_ROW)   // 34816
#define B_TILE_BYTES (N_TILE * SMEM_ROW)   // 21760
#define STAGE_BYTES  (A_TILE_BYTES + B_TILE_BYTES)       // 56576
#define SMEM_TOTAL   (NSTAGES * STAGE_BYTES)             // 226304

#define B_OFF  A_TILE_BYTES

// ---- scratch (no cudaMalloc allowed) ----
__device__ __align__(1024) __half g_xh[M_ROWS * K_DIM];

// ============================================================================
// helpers
// ============================================================================
__device__ __forceinline__ uint32_t smem_u32(const void* p) {
    uint32_t a;
    asm("{ .reg .u64 t; cvta.to.shared.u64 t, %1; cvt.u32.u64 %0, t; }"
        : "=r"(a) : "l"(p));
    return a;
}
__device__ __forceinline__ void cp16(uint32_t dst, const void* src) {
    asm volatile("cp.async.cg.shared.global [%0], [%1], 16;"
                 :: "r"(dst), "l"(src) : "memory");
}
__device__ __forceinline__ void cp_commit() {
    asm volatile("cp.async.commit_group;" ::: "memory");
}
template <int N>
__device__ __forceinline__ void cp_wait() {
    asm volatile("cp.async.wait_group %0;" :: "n"(N) : "memory");
}
__device__ __forceinline__ void ldsm_x4(uint32_t* r, uint32_t addr) {
    asm volatile("ldmatrix.sync.aligned.m8n8.x4.shared.b16 {%0,%1,%2,%3}, [%4];"
                 : "=r"(r[0]), "=r"(r[1]), "=r"(r[2]), "=r"(r[3]) : "r"(addr));
}
__device__ __forceinline__ void mma_f16(float* d, const uint32_t* a, const uint32_t* b) {
    asm volatile(
        "mma.sync.aligned.m16n8k16.row.col.f32.f16.f16.f32 "
        "{%0,%1,%2,%3}, {%4,%5,%6,%7}, {%8,%9}, {%0,%1,%2,%3};"
        : "+f"(d[0]), "+f"(d[1]), "+f"(d[2]), "+f"(d[3])
        : "r"(a[0]), "r"(a[1]), "r"(a[2]), "r"(a[3]), "r"(b[0]), "r"(b[1]));
}
__device__ __forceinline__ uint32_t i2h2(int lo, int hi) {
    __half2 h = __halves2half2(__int2half_rn(lo), __int2half_rn(hi));
    return *reinterpret_cast<uint32_t*>(&h);
}

// ============================================================================
// Kernel 1: x (fp32) -> fp16
// ============================================================================
__global__ __launch_bounds__(512) void cvt_x_kernel(const float* __restrict__ x) {
    int idx = (blockIdx.x * 512 + threadIdx.x) * 8;
    float4 v0 = *reinterpret_cast<const float4*>(x + idx);
    float4 v1 = *reinterpret_cast<const float4*>(x + idx + 4);
    __half2 h[4];
    h[0] = __floats2half2_rn(v0.x, v0.y);
    h[1] = __floats2half2_rn(v0.z, v0.w);
    h[2] = __floats2half2_rn(v1.x, v1.y);
    h[3] = __floats2half2_rn(v1.z, v1.w);
    *reinterpret_cast<uint4*>(g_xh + idx) = *reinterpret_cast<uint4*>(h);
}

// ============================================================================
// Kernel 2: GEMM. 138 CTAs x 640 threads. CTA tile 128(M) x 80(N).
// 4x5 warp grid, warp tile 32x16. ldmatrix.x4 fragments, prefetch ks+1.
// ============================================================================
__global__ __launch_bounds__(NTHREADS, 1) void gemm_f16_kernel(
    const int* __restrict__ w32,
    const float* __restrict__ scale,
    const float* __restrict__ bias,
    float* __restrict__ out)
{
    extern __shared__ char smem[];
    const uint32_t sb = smem_u32(smem);
    const int tid = threadIdx.x;
    const int lane = tid & 31;
    const int wid = tid >> 5;
    const int wm = wid & 3;        // warp M index (0..3)
    const int wn = wid >> 2;       // warp N index (0..4)
    const int n_base = blockIdx.x * N_TILE;

    // ---- A-side cp.async (threads 0..511, 4 x 16B per stage) ---------------
    uint32_t cpA_dst[4];
    const __half* cpA_src[4];
    if (tid < 512) {
#pragma unroll
        for (int i = 0; i < 4; i++) {
            int c = tid + i * 512;           // [0, 2048)
            int r = c >> 4;                  // m row 0..127
            int col = (c & 15) * 16;         // byte col 0..240
            cpA_dst[i] = sb + r * SMEM_ROW + col;
            cpA_src[i] = g_xh + (size_t)r * K_DIM + col / 2;
        }
    }
    auto issueA = [&](int s) {
        if (tid < 512) {
            uint32_t buf_off = (uint32_t)((s & (NSTAGES - 1)) * STAGE_BYTES);
            int k0 = s * K_STAGE;
#pragma unroll
            for (int i = 0; i < 4; i++)
                cp16(cpA_dst[i] + buf_off, cpA_src[i] + k0);
            cp_commit();
        }
    };

    // ---- B-side: 4 x LDG.128 per thread per stage --------------------------
    const int wr = tid >> 5;            // 0..19
    const int c4 = lane * 4;            // int32 (k) index
    const int* wsrc[4];
#pragma unroll
    for (int j = 0; j < 4; j++) {
        int rg = n_base + wr + 20 * j;
        if (rg > N_DIM - 1) rg = N_DIM - 1;   // clamp (ragged last tile)
        wsrc[j] = w32 + (size_t)rg * K_DIM + c4;
    }

    int4 breg[4];
    auto ldgB = [&](int s) {
        const int k0 = s * K_STAGE;
#pragma unroll
        for (int j = 0; j < 4; j++)
            breg[j] = *reinterpret_cast<const int4*>(wsrc[j] + k0);
    };
    auto stsB = [&](int s) {
        char* dst = smem + (s & (NSTAGES - 1)) * STAGE_BYTES + B_OFF
                         + wr * SMEM_ROW + lane * 8;
#pragma unroll
        for (int j = 0; j < 4; j++) {
            uint2 hv;
            hv.x = i2h2(breg[j].x, breg[j].y);
            hv.y = i2h2(breg[j].z, breg[j].w);
            *reinterpret_cast<uint2*>(dst + j * 20 * SMEM_ROW) = hv;
        }
    };

    // ---- prologue: stages 0,1 ----------------------------------------------
    issueA(0);
    issueA(1);
    ldgB(0); stsB(0);
    ldgB(1); stsB(1);

    // ---- ldmatrix per-lane addresses ----------------------------------------
    // A x4: matrices {m0:rows0-7 k0-7, m1:rows8-15 k0-7, m2:rows0-7 k8-15, m3:rows8-15 k8-15}
    //   -> r0..r3 = a0..a3 of mma.m16n8k16 A fragment.
    const int aRow  = lane & 15;
    const int aKoff = (lane >> 4) * 16;
    // B x4: {m0:n0-7 k0-7, m1:n0-7 k8-15, m2:n8-15 k0-7, m3:n8-15 k8-15}
    //   -> {r0,r1} = B operand n-group0, {r2,r3} = n-group1.
    const int bRow  = (lane & 7) | ((lane >> 4) << 3);
    const int bKoff = ((lane >> 3) & 1) * 16;

    const uint32_t aAddr = sb + (uint32_t)((wm * 32 + aRow) * SMEM_ROW + aKoff);
    const uint32_t bAddr = sb + (uint32_t)B_OFF
                         + (uint32_t)((wn * 16 + bRow) * SMEM_ROW + bKoff);

    float acc[2][2][4] = {};

    // ---- main loop ---------------------------------------------------------
    for (int s = 0; s < NUM_STEPS; s++) {
        cp_wait<1>();          // A stage s landed
        __syncthreads();       // publish everyone's A + B(stage s)

        if (s + 2 < NUM_STEPS) { ldgB(s + 2); issueA(s + 2); }
        else if (tid < 512)    { cp_commit(); }   // keep wait accounting sound

        const uint32_t buf = (uint32_t)((s & (NSTAGES - 1)) * STAGE_BYTES);

        uint32_t afc[2][4], bfc[4];   // current fragments
        uint32_t afn[2][4], bfn[4];   // next fragments
        ldsm_x4(afc[0], aAddr + buf);
        ldsm_x4(afc[1], aAddr + buf + 16 * SMEM_ROW);
        ldsm_x4(bfc,    bAddr + buf);

#pragma unroll
        for (int ks = 0; ks < 8; ks++) {          // 8 x k16 per stage
            if (ks < 7) {
                const uint32_t off = buf + (ks + 1) * 32;
                ldsm_x4(afn[0], aAddr + off);
                ldsm_x4(afn[1], aAddr + off + 16 * SMEM_ROW);
                ldsm_x4(bfn,    bAddr + off);
            }
#pragma unroll
            for (int mf = 0; mf < 2; mf++) {
                mma_f16(acc[mf][0], afc[mf], bfc);
                mma_f16(acc[mf][1], afc[mf], bfc + 2);
            }
            if (ks < 7) {
#pragma unroll
                for (int mf = 0; mf < 2; mf++)
#pragma unroll
                    for (int r = 0; r < 4; r++) afc[mf][r] = afn[mf][r];
#pragma unroll
                for (int r = 0; r < 4; r++) bfc[r] = bfn[r];
            }
        }

        if (s + 2 < NUM_STEPS) stsB(s + 2);   // ring distance 2 (!= s mod 4)
    }

    // ---- epilogue ----------------------------------------------------------
    const float sw = __ldg(scale);
    const int g = lane >> 2;
    const int mrow0 = wm * 32 + g;
#pragma unroll
    for (int mf = 0; mf < 2; mf++) {
        int m0 = mrow0 + mf * 16;
#pragma unroll
        for (int nf = 0; nf < 2; nf++) {
            int n = n_base + wn * 16 + nf * 8 + 2 * (lane & 3);
            if (n < N_DIM) {
                float2 bv = __ldg(reinterpret_cast<const float2*>(bias + n));
                float2 o0, o1;
                o0.x = acc[mf][nf][0] * sw + bv.x;
                o0.y = acc[mf][nf][1] * sw + bv.y;
                o1.x = acc[mf][nf][2] * sw + bv.x;
                o1.y = acc[mf][nf][3] * sw + bv.y;
                *reinterpret_cast<float2*>(out + (size_t)m0 * N_DIM + n) = o0;
                *reinterpret_cast<float2*>(out + (size_t)(m0 + 8) * N_DIM + n) = o1;
            }
        }
    }
}

// ============================================================================
// Host launcher — inputs identified by element count (order-robust)
// ============================================================================
extern "C" void kernel_launch(void* const* d_in, const int* in_sizes, int n_in,
                              void* d_out, int out_size) {
    const float* x     = nullptr;
    const int*   w32   = nullptr;    // int8 weights widened to int32 by harness
    const float* scale = nullptr;
    const float* bias  = nullptr;
    for (int i = 0; i < n_in; i++) {
        switch (in_sizes[i]) {
            case M_ROWS * K_DIM: x     = (const float*)d_in[i]; break;  // 524288
            case N_DIM * K_DIM:  w32   = (const int*)d_in[i];   break;  // 45088768
            case 1:              scale = (const float*)d_in[i]; break;
            case N_DIM:          bias  = (const float*)d_in[i]; break;  // 11008
        }
    }
    float* out = (float*)d_out;

    cudaFuncSetAttribute(gemm_f16_kernel,
                         cudaFuncAttributeMaxDynamicSharedMemorySize, SMEM_TOTAL);

    cvt_x_kernel<<<M_ROWS, 512>>>(x);
    gemm_f16_kernel<<<N_BLOCKS, NTHREADS, SMEM_TOTAL>>>(w32, scale, bias, out);
}

// round 10
// speedup vs baseline: 2.5335x; 1.0388x over previous
#include <cuda_runtime.h>
#include <cuda_fp16.h>
#include <cstdint>

// ============================================================================
// y[128, 11008] = x[128,4096] @ W[11008,4096]^T * scale + bias
// w_q arrives as int32 (harness widens int8 -> int32).
// fp16 single-pass: x -> fp16 (rel err ~2e-4), W int8 exact in fp16.
// mma.sync.m16n8k16 + ldmatrix.x4 fragments.
// R9: 2 CTAs/SM. CTA tile 64(M) x 80(N), grid 276, 320 threads (2Mx5N warps,
// warp tile 32x16), NSTAGES=2, smem 78336/CTA, launch_bounds(320,2).
// Cross-CTA overlap covers barrier + scoreboard bubbles.
// ============================================================================

#define M_ROWS 128
#define M_TILE 64
#define K_DIM  4096
#define N_DIM  11008
#define N_TILE 80
#define N_COLS 138
#define N_BLOCKS (2 * N_COLS)              // 276
#define K_STAGE 128                        // k elements per stage
#define NSTAGES 2
#define NUM_STEPS (K_DIM / K_STAGE)        // 32
#define NTHREADS 320

#define SMEM_ROW 272                       // 256B data + 16 pad
#define A_TILE_BYTES (M_TILE * SMEM_ROW)   // 17408
#define B_TILE_BYTES (N_TILE * SMEM_ROW)   // 21760
#define STAGE_BYTES  (A_TILE_BYTES + B_TILE_BYTES)       // 39168
#define SMEM_TOTAL   (NSTAGES * STAGE_BYTES)             // 78336 -> 2 CTAs/SM

#define B_OFF  A_TILE_BYTES

// ---- scratch (no cudaMalloc allowed) ----
__device__ __align__(1024) __half g_xh[M_ROWS * K_DIM];

// ============================================================================
// helpers
// ============================================================================
__device__ __forceinline__ uint32_t smem_u32(const void* p) {
    uint32_t a;
    asm("{ .reg .u64 t; cvta.to.shared.u64 t, %1; cvt.u32.u64 %0, t; }"
        : "=r"(a) : "l"(p));
    return a;
}
__device__ __forceinline__ void cp16(uint32_t dst, const void* src) {
    asm volatile("cp.async.cg.shared.global [%0], [%1], 16;"
                 :: "r"(dst), "l"(src) : "memory");
}
__device__ __forceinline__ void cp_commit() {
    asm volatile("cp.async.commit_group;" ::: "memory");
}
template <int N>
__device__ __forceinline__ void cp_wait() {
    asm volatile("cp.async.wait_group %0;" :: "n"(N) : "memory");
}
__device__ __forceinline__ void ldsm_x4(uint32_t* r, uint32_t addr) {
    asm volatile("ldmatrix.sync.aligned.m8n8.x4.shared.b16 {%0,%1,%2,%3}, [%4];"
                 : "=r"(r[0]), "=r"(r[1]), "=r"(r[2]), "=r"(r[3]) : "r"(addr));
}
__device__ __forceinline__ void mma_f16(float* d, const uint32_t* a, const uint32_t* b) {
    asm volatile(
        "mma.sync.aligned.m16n8k16.row.col.f32.f16.f16.f32 "
        "{%0,%1,%2,%3}, {%4,%5,%6,%7}, {%8,%9}, {%0,%1,%2,%3};"
        : "+f"(d[0]), "+f"(d[1]), "+f"(d[2]), "+f"(d[3])
        : "r"(a[0]), "r"(a[1]), "r"(a[2]), "r"(a[3]), "r"(b[0]), "r"(b[1]));
}
__device__ __forceinline__ uint32_t i2h2(int lo, int hi) {
    __half2 h = __halves2half2(__int2half_rn(lo), __int2half_rn(hi));
    return *reinterpret_cast<uint32_t*>(&h);
}

// ============================================================================
// Kernel 1: x (fp32) -> fp16
// ============================================================================
__global__ __launch_bounds__(512) void cvt_x_kernel(const float* __restrict__ x) {
    int idx = (blockIdx.x * 512 + threadIdx.x) * 8;
    float4 v0 = *reinterpret_cast<const float4*>(x + idx);
    float4 v1 = *reinterpret_cast<const float4*>(x + idx + 4);
    __half2 h[4];
    h[0] = __floats2half2_rn(v0.x, v0.y);
    h[1] = __floats2half2_rn(v0.z, v0.w);
    h[2] = __floats2half2_rn(v1.x, v1.y);
    h[3] = __floats2half2_rn(v1.z, v1.w);
    *reinterpret_cast<uint4*>(g_xh + idx) = *reinterpret_cast<uint4*>(h);
}

// ============================================================================
// Kernel 2: GEMM. 276 CTAs x 320 threads, 2 CTAs/SM. CTA tile 64(M) x 80(N).
// 2x5 warp grid, warp tile 32x16, ldmatrix.x4, frag prefetch ks+1.
// Per-step schedule: sync; stsB(s+1); issueA(s+1); ldg_h0(s+2);
//   ks0-2; pack_h0; ldg_h1(s+2); ks3-6; pack_h1; ks7.
// ============================================================================
__global__ void __launch_bounds__(NTHREADS, 2) gemm_f16_kernel(
    const int* __restrict__ w32,
    const float* __restrict__ scale,
    const float* __restrict__ bias,
    float* __restrict__ out)
{
    extern __shared__ char smem[];
    const uint32_t sb = smem_u32(smem);
    const int tid = threadIdx.x;
    const int lane = tid & 31;
    const int wid = tid >> 5;
    const int wm = wid & 1;        // warp M index (0..1)
    const int wn = wid >> 1;       // warp N index (0..4)
    const int bx = blockIdx.x;
    const int n_base = (bx >> 1) * N_TILE;
    const int m_base = (bx & 1) * M_TILE;

    // ---- A-side cp.async (threads 0..255, 4 x 16B per stage) ---------------
    // A stage = 64 rows x 256 bytes = 1024 chunks of 16B.
    uint32_t cpA_dst[4];
    const __half* cpA_src[4];
    if (tid < 256) {
#pragma unroll
        for (int i = 0; i < 4; i++) {
            int c = tid + i * 256;           // [0, 1024)
            int r = c >> 4;                  // m row 0..63
            int col = (c & 15) * 16;         // byte col 0..240
            cpA_dst[i] = sb + r * SMEM_ROW + col;
            cpA_src[i] = g_xh + (size_t)(m_base + r) * K_DIM + col / 2;
        }
    }
    auto issueA = [&](int s) {
        if (tid < 256) {
            uint32_t buf_off = (uint32_t)((s & (NSTAGES - 1)) * STAGE_BYTES);
            int k0 = s * K_STAGE;            // halves: 128 h = 256 B per stage
#pragma unroll
            for (int i = 0; i < 4; i++)
                cp16(cpA_dst[i] + buf_off, cpA_src[i] + k0);
            cp_commit();
        }
    };

    // ---- B-side: 8 rows per thread (wr + 10j), k = lane*4 ------------------
    const int wr = tid >> 5;            // 0..9
    const int klane = lane * 4;         // int32 index within W row
    int4 raw[4];
    uint2 pk[8];

    auto ldg_half = [&](int s, int h) {
        const int k0 = s * K_STAGE + klane;
#pragma unroll
        for (int j = 0; j < 4; j++) {
            int rg = n_base + wr + 10 * (h * 4 + j);
            if (rg > N_DIM - 1) rg = N_DIM - 1;   // clamp (ragged last column)
            raw[j] = *reinterpret_cast<const int4*>(w32 + (size_t)rg * K_DIM + k0);
        }
    };
    auto pack_half = [&](int h) {
#pragma unroll
        for (int j = 0; j < 4; j++) {
            pk[h * 4 + j].x = i2h2(raw[j].x, raw[j].y);
            pk[h * 4 + j].y = i2h2(raw[j].z, raw[j].w);
        }
    };
    auto stsB = [&](int s) {
        char* dst = smem + (s & (NSTAGES - 1)) * STAGE_BYTES + B_OFF
                         + wr * SMEM_ROW + lane * 8;
#pragma unroll
        for (int j = 0; j < 8; j++)
            *reinterpret_cast<uint2*>(dst + j * 10 * SMEM_ROW) = pk[j];
    };

    // ---- prologue: B stage 0 to smem, B stage 1 in regs, A stage 0 --------
    ldg_half(0, 0); pack_half(0);
    ldg_half(0, 1); pack_half(1);
    stsB(0);
    ldg_half(1, 0); pack_half(0);
    ldg_half(1, 1); pack_half(1);
    issueA(0);

    // ---- ldmatrix per-lane addresses ---------------------------------------
    const int aRow  = lane & 15;
    const int aKoff = (lane >> 4) * 16;
    const int bRow  = (lane & 7) | ((lane >> 4) << 3);
    const int bKoff = ((lane >> 3) & 1) * 16;
    const uint32_t aAddr = sb + (uint32_t)((wm * 32 + aRow) * SMEM_ROW + aKoff);
    const uint32_t bAddr = sb + (uint32_t)B_OFF
                         + (uint32_t)((wn * 16 + bRow) * SMEM_ROW + bKoff);

    float acc[2][2][4] = {};
    uint32_t afc[2][4], bfc[4], afn[2][4], bfn[4];

    // ---- main loop ---------------------------------------------------------
    for (int s = 0; s < NUM_STEPS; s++) {
        cp_wait<0>();          // this thread's A groups all landed
        __syncthreads();       // publish A(s) + everyone's B(s) STS

        if (s + 1 < NUM_STEPS) { stsB(s + 1); issueA(s + 1); }
        if (s + 2 < NUM_STEPS) ldg_half(s + 2, 0);

        const uint32_t buf = (uint32_t)((s & (NSTAGES - 1)) * STAGE_BYTES);
        ldsm_x4(afc[0], aAddr + buf);
        ldsm_x4(afc[1], aAddr + buf + 16 * SMEM_ROW);
        ldsm_x4(bfc,    bAddr + buf);

#pragma unroll
        for (int ks = 0; ks < 8; ks++) {          // 8 x k16 per stage
            if (ks < 7) {
                const uint32_t off = buf + (ks + 1) * 32;
                ldsm_x4(afn[0], aAddr + off);
                ldsm_x4(afn[1], aAddr + off + 16 * SMEM_ROW);
                ldsm_x4(bfn,    bAddr + off);
            }
#pragma unroll
            for (int mf = 0; mf < 2; mf++) {
                mma_f16(acc[mf][0], afc[mf], bfc);
                mma_f16(acc[mf][1], afc[mf], bfc + 2);
            }
            if (ks == 2) {
                if (s + 2 < NUM_STEPS) { pack_half(0); ldg_half(s + 2, 1); }
            }
            if (ks == 6) {
                if (s + 2 < NUM_STEPS) pack_half(1);
            }
            if (ks < 7) {
#pragma unroll
                for (int mf = 0; mf < 2; mf++)
#pragma unroll
                    for (int r = 0; r < 4; r++) afc[mf][r] = afn[mf][r];
#pragma unroll
                for (int r = 0; r < 4; r++) bfc[r] = bfn[r];
            }
        }
    }

    // ---- epilogue ----------------------------------------------------------
    const float sw = __ldg(scale);
    const int g = lane >> 2;
    const int mrow0 = m_base + wm * 32 + g;
#pragma unroll
    for (int mf = 0; mf < 2; mf++) {
        int m0 = mrow0 + mf * 16;
#pragma unroll
        for (int nf = 0; nf < 2; nf++) {
            int n = n_base + wn * 16 + nf * 8 + 2 * (lane & 3);
            if (n < N_DIM) {
                float2 bv = __ldg(reinterpret_cast<const float2*>(bias + n));
                float2 o0, o1;
                o0.x = acc[mf][nf][0] * sw + bv.x;
                o0.y = acc[mf][nf][1] * sw + bv.y;
                o1.x = acc[mf][nf][2] * sw + bv.x;
                o1.y = acc[mf][nf][3] * sw + bv.y;
                *reinterpret_cast<float2*>(out + (size_t)m0 * N_DIM + n) = o0;
                *reinterpret_cast<float2*>(out + (size_t)(m0 + 8) * N_DIM + n) = o1;
            }
        }
    }
}

// ============================================================================
// Host launcher — inputs identified by element count (order-robust)
// ============================================================================
extern "C" void kernel_launch(void* const* d_in, const int* in_sizes, int n_in,
                              void* d_out, int out_size) {
    const float* x     = nullptr;
    const int*   w32   = nullptr;    // int8 weights widened to int32 by harness
    const float* scale = nullptr;
    const float* bias  = nullptr;
    for (int i = 0; i < n_in; i++) {
        switch (in_sizes[i]) {
            case M_ROWS * K_DIM: x     = (const float*)d_in[i]; break;  // 524288
            case N_DIM * K_DIM:  w32   = (const int*)d_in[i];   break;  // 45088768
            case 1:              scale = (const float*)d_in[i]; break;
            case N_DIM:          bias  = (const float*)d_in[i]; break;  // 11008
        }
    }
    float* out = (float*)d_out;

    cudaFuncSetAttribute(gemm_f16_kernel,
                         cudaFuncAttributeMaxDynamicSharedMemorySize, SMEM_TOTAL);

    cvt_x_kernel<<<M_ROWS, 512>>>(x);
    gemm_f16_kernel<<<N_BLOCKS, NTHREADS, SMEM_TOTAL>>>(w32, scale, bias, out);
}